// round 2
// baseline (speedup 1.0000x reference)
#include <cuda_runtime.h>

// S4D kernel generation:
//   K[h,l] = 2 * Re( sum_n dC[h,n] * dA[h,n]^l ),  h in [0,1024), l in [0,4096), n in [0,32)
// R2: pack mode pairs into f32x2 (FFMA2) — sm_103a packed fp32, PTX-only.
// Recurrence w <- w*dA done as elementwise packed complex mul over 16 pairs.

#define HN   1024   // H
#define NM   32     // N/2 modes
#define NP   (NM/2) // packed pairs
#define LL   4096
#define TPB  64
#define CHUNK (LL / TPB)  // 64
#define LOG2_TPB 6

typedef unsigned long long u64;

__device__ __forceinline__ u64 pack2(float lo, float hi) {
    u64 r; asm("mov.b64 %0, {%1,%2};" : "=l"(r) : "f"(lo), "f"(hi)); return r;
}
__device__ __forceinline__ void unpack2(float& lo, float& hi, u64 v) {
    asm("mov.b64 {%0,%1}, %2;" : "=f"(lo), "=f"(hi) : "l"(v));
}
__device__ __forceinline__ u64 mul2(u64 a, u64 b) {
    u64 d; asm("mul.rn.f32x2 %0, %1, %2;" : "=l"(d) : "l"(a), "l"(b)); return d;
}
__device__ __forceinline__ u64 add2(u64 a, u64 b) {
    u64 d; asm("add.rn.f32x2 %0, %1, %2;" : "=l"(d) : "l"(a), "l"(b)); return d;
}
__device__ __forceinline__ u64 fma2(u64 a, u64 b, u64 c) {
    u64 d; asm("fma.rn.f32x2 %0, %1, %2, %3;" : "=l"(d) : "l"(a), "l"(b), "l"(c)); return d;
}

__global__ void __launch_bounds__(TPB)
s4d_vandermonde_kernel(const float* __restrict__ log_dt,      // (H)
                       const float* __restrict__ C_real,      // (1,H,NM,2)
                       const float* __restrict__ log_A_real,  // (H,NM)
                       const float* __restrict__ A_imag,      // (H,NM)
                       float* __restrict__ out)               // (1,H,L)
{
    const int h = blockIdx.x;
    const int t = threadIdx.x;

    __shared__ float s_dAr[NM], s_dAi[NM], s_dCr[NM], s_dCi[NM];
    // S[j][n] = dA_n ^ (CHUNK * 2^j)
    __shared__ float s_Sr[LOG2_TPB][NM], s_Si[LOG2_TPB][NM];

    if (t < NM) {
        const int n = t;
        const float dt = expf(log_dt[h]);
        const float Ar = -expf(log_A_real[h * NM + n]);
        const float Ai = A_imag[h * NM + n];
        const float dtAr = Ar * dt;
        const float dtAi = Ai * dt;
        const float denr = 1.0f - 0.5f * dtAr;
        const float deni = -0.5f * dtAi;
        const float inv  = 1.0f / (denr * denr + deni * deni);
        const float Br = dt * denr * inv;
        const float Bi = -dt * deni * inv;
        const float Cr = C_real[(h * NM + n) * 2 + 0];
        const float Ci = C_real[(h * NM + n) * 2 + 1];
        s_dCr[n] = Cr * Br - Ci * Bi;
        s_dCi[n] = Cr * Bi + Ci * Br;
        const float numr = 1.0f + 0.5f * dtAr;
        const float numi = 0.5f * dtAi;
        const float dAr = (numr * denr + numi * deni) * inv;
        const float dAi = (numi * denr - numr * deni) * inv;
        s_dAr[n] = dAr;
        s_dAi[n] = dAi;
        // dA^CHUNK via 6 squarings
        float pr = dAr, pi = dAi;
        #pragma unroll
        for (int j = 0; j < 6; ++j) {
            const float nr = pr * pr - pi * pi;
            const float ni = 2.0f * pr * pi;
            pr = nr; pi = ni;
        }
        #pragma unroll
        for (int j = 0; j < LOG2_TPB; ++j) {
            s_Sr[j][n] = pr;
            s_Si[j][n] = pi;
            const float nr = pr * pr - pi * pi;
            const float ni = 2.0f * pr * pi;
            pr = nr; pi = ni;
        }
    }
    __syncthreads();

    // Packed constants: Ar/Ai/NAi (=-Ai) per pair, and packed state Wr/Wi.
    u64 Ar[NP], Ai[NP], NAi[NP], Wr[NP], Wi[NP];

    #pragma unroll
    for (int p = 0; p < NP; ++p) {
        const int n = 2 * p;
        Ar[p]  = pack2(s_dAr[n],  s_dAr[n + 1]);
        Ai[p]  = pack2(s_dAi[n],  s_dAi[n + 1]);
        NAi[p] = pack2(-s_dAi[n], -s_dAi[n + 1]);
        Wr[p]  = pack2(s_dCr[n],  s_dCr[n + 1]);
        Wi[p]  = pack2(s_dCi[n],  s_dCi[n + 1]);
    }

    // Advance W to l = t*CHUNK via binary ladder (packed complex mul).
    #pragma unroll
    for (int j = 0; j < LOG2_TPB; ++j) {
        if ((t >> j) & 1) {
            #pragma unroll
            for (int p = 0; p < NP; ++p) {
                const int n = 2 * p;
                const u64 Sr  = pack2(s_Sr[j][n],  s_Sr[j][n + 1]);
                const u64 Si  = pack2(s_Si[j][n],  s_Si[j][n + 1]);
                const u64 NSi = pack2(-s_Si[j][n], -s_Si[j][n + 1]);
                const u64 t1 = mul2(Wi[p], NSi);
                const u64 t2 = mul2(Wi[p], Sr);
                const u64 nr = fma2(Wr[p], Sr, t1);
                Wi[p] = fma2(Wr[p], Si, t2);
                Wr[p] = nr;
            }
        }
    }

    float* __restrict__ o = out + (size_t)h * LL + t * CHUNK;

    // Mainloop: per step, emit 2*sum Re(W), then W *= dA (packed).
    for (int s = 0; s < CHUNK; s += 4) {
        float res[4];
        #pragma unroll
        for (int q = 0; q < 4; ++q) {
            // packed reduction over 16 pairs, 4 accumulators
            u64 a0 = Wr[0], a1 = Wr[1], a2 = Wr[2], a3 = Wr[3];
            #pragma unroll
            for (int p = 4; p < NP; p += 4) {
                a0 = add2(a0, Wr[p + 0]);
                a1 = add2(a1, Wr[p + 1]);
                a2 = add2(a2, Wr[p + 2]);
                a3 = add2(a3, Wr[p + 3]);
            }
            a0 = add2(a0, a1);
            a2 = add2(a2, a3);
            a0 = add2(a0, a2);
            float lo, hi;
            unpack2(lo, hi, a0);
            res[q] = 2.0f * (lo + hi);
            // packed complex recurrence
            #pragma unroll
            for (int p = 0; p < NP; ++p) {
                const u64 t1 = mul2(Wi[p], NAi[p]);
                const u64 t2 = mul2(Wi[p], Ar[p]);
                const u64 nr = fma2(Wr[p], Ar[p], t1);
                Wi[p] = fma2(Wr[p], Ai[p], t2);
                Wr[p] = nr;
            }
        }
        *reinterpret_cast<float4*>(o + s) = make_float4(res[0], res[1], res[2], res[3]);
    }
}

extern "C" void kernel_launch(void* const* d_in, const int* in_sizes, int n_in,
                              void* d_out, int out_size) {
    const float* log_dt     = (const float*)d_in[0];
    const float* C_real     = (const float*)d_in[1];
    const float* log_A_real = (const float*)d_in[2];
    const float* A_imag     = (const float*)d_in[3];
    float* out = (float*)d_out;
    s4d_vandermonde_kernel<<<HN, TPB>>>(log_dt, C_real, log_A_real, A_imag, out);
}

// round 3
// speedup vs baseline: 1.1606x; 1.1606x over previous
#include <cuda_runtime.h>

// S4D kernel generation:
//   K[h,l] = 2 * Re( sum_n dC[h,n] * dA[h,n]^l ),  h in [0,1024), l in [0,4096), n in [0,32)
// R3: real 2nd-order (Chebyshev-like) recurrence per mode:
//   k[l+1] = 2Re(dA)*k[l] - |dA|^2*k[l-1]   -> 2 FMA ops/mode/step (vs 4 for complex mul)
// Complex binary ladder only for chunk-start seeds. Grid split 2x along L for occupancy.

#define HN    1024   // H
#define NM    32     // N/2 modes
#define LL    4096
#define TPB   64
#define SPLIT 2                      // L-splits per channel
#define CHUNK (LL / (TPB * SPLIT))   // 32 contiguous l's per thread
#define NLAD  7                      // ladder levels: dA^(CHUNK * 2^j), j=0..6 covers T<128

__global__ void __launch_bounds__(TPB)
s4d_cheb_kernel(const float* __restrict__ log_dt,      // (H)
                const float* __restrict__ C_real,      // (1,H,NM,2)
                const float* __restrict__ log_A_real,  // (H,NM)
                const float* __restrict__ A_imag,      // (H,NM)
                float* __restrict__ out)               // (1,H,L)
{
    const int h    = blockIdx.x >> 1;
    const int half = blockIdx.x & 1;
    const int t    = threadIdx.x;
    const int T    = t + TPB * half;   // chunk index in [0,128)

    __shared__ float s_dAr[NM], s_dAi[NM], s_dCr[NM], s_dCi[NM];
    __shared__ float s_a2[NM], s_nm[NM];               // 2*Re(dA), -|dA|^2
    __shared__ float s_Sr[NLAD][NM], s_Si[NLAD][NM];   // dA^(CHUNK*2^j)

    if (t < NM) {
        const int n = t;
        const float dt = expf(log_dt[h]);
        const float Ar = -expf(log_A_real[h * NM + n]);
        const float Ai = A_imag[h * NM + n];
        const float dtAr = Ar * dt;
        const float dtAi = Ai * dt;
        const float denr = 1.0f - 0.5f * dtAr;
        const float deni = -0.5f * dtAi;
        const float inv  = 1.0f / (denr * denr + deni * deni);
        const float Br = dt * denr * inv;
        const float Bi = -dt * deni * inv;
        const float Cr = C_real[(h * NM + n) * 2 + 0];
        const float Ci = C_real[(h * NM + n) * 2 + 1];
        // dC scaled by 2 so k = Re(W) directly includes the factor 2
        s_dCr[n] = 2.0f * (Cr * Br - Ci * Bi);
        s_dCi[n] = 2.0f * (Cr * Bi + Ci * Br);
        const float numr = 1.0f + 0.5f * dtAr;
        const float numi = 0.5f * dtAi;
        const float dAr = (numr * denr + numi * deni) * inv;
        const float dAi = (numi * denr - numr * deni) * inv;
        s_dAr[n] = dAr;
        s_dAi[n] = dAi;
        s_a2[n]  = 2.0f * dAr;
        s_nm[n]  = -(dAr * dAr + dAi * dAi);
        // p = dA^CHUNK (CHUNK = 32 = 2^5)
        float pr = dAr, pi = dAi;
        #pragma unroll
        for (int j = 0; j < 5; ++j) {
            const float nr = pr * pr - pi * pi;
            const float ni = 2.0f * pr * pi;
            pr = nr; pi = ni;
        }
        // ladder S_j = dA^(CHUNK * 2^j), j = 0..NLAD-1
        #pragma unroll
        for (int j = 0; j < NLAD; ++j) {
            s_Sr[j][n] = pr;
            s_Si[j][n] = pi;
            const float nr = pr * pr - pi * pi;
            const float ni = 2.0f * pr * pi;
            pr = nr; pi = ni;
        }
    }
    __syncthreads();

    // Per-thread state: rolling pair (ka, kb) + recurrence coefficients.
    float ka[NM], kb[NM], a2[NM], nm[NM];

    #pragma unroll
    for (int n = 0; n < NM; ++n) {
        a2[n] = s_a2[n];
        nm[n] = s_nm[n];
        // W = dC * dA^(T*CHUNK) via binary ladder
        float xr = s_dCr[n];
        float xi = s_dCi[n];
        #pragma unroll
        for (int j = 0; j < NLAD; ++j) {
            if ((T >> j) & 1) {
                const float sr = s_Sr[j][n];
                const float si = s_Si[j][n];
                const float nr = xr * sr - xi * si;
                const float ni = xr * si + xi * sr;
                xr = nr; xi = ni;
            }
        }
        // seeds: k[l0] = Re(W), k[l0+1] = Re(W * dA)
        ka[n] = xr;
        kb[n] = xr * s_dAr[n] - xi * s_dAi[n];
    }

    float* __restrict__ o = out + (size_t)h * LL + T * CHUNK;

    // Mainloop: per step emit sum_n ka[n], then advance:
    //   knew = a2*kb + nm*ka ; ka <- kb ; kb <- knew      (2 FMA-pipe ops/mode)
    for (int s = 0; s < CHUNK; s += 4) {
        float res[4];
        #pragma unroll
        for (int q = 0; q < 4; ++q) {
            float r0 = ka[0], r1 = ka[1], r2 = ka[2], r3 = ka[3];
            #pragma unroll
            for (int n = 4; n < NM; n += 4) {
                r0 += ka[n + 0];
                r1 += ka[n + 1];
                r2 += ka[n + 2];
                r3 += ka[n + 3];
            }
            res[q] = (r0 + r1) + (r2 + r3);
            #pragma unroll
            for (int n = 0; n < NM; ++n) {
                const float knew = fmaf(nm[n], ka[n], a2[n] * kb[n]);
                ka[n] = kb[n];
                kb[n] = knew;
            }
        }
        *reinterpret_cast<float4*>(o + s) = make_float4(res[0], res[1], res[2], res[3]);
    }
}

extern "C" void kernel_launch(void* const* d_in, const int* in_sizes, int n_in,
                              void* d_out, int out_size) {
    const float* log_dt     = (const float*)d_in[0];
    const float* C_real     = (const float*)d_in[1];
    const float* log_A_real = (const float*)d_in[2];
    const float* A_imag     = (const float*)d_in[3];
    float* out = (float*)d_out;
    s4d_cheb_kernel<<<HN * SPLIT, TPB>>>(log_dt, C_real, log_A_real, A_imag, out);
}

// round 6
// speedup vs baseline: 1.7938x; 1.5456x over previous
#include <cuda_runtime.h>
#include <cstdint>

// S4D kernel generation as 1024 per-CTA bf16 HMMA GEMMs (tcgen05 unavailable:
// harness PTX targets base sm_103; mma.sync is arch-neutral).
//   l = 32u + v, u in [0,128), v in [0,32)
//   K[h,l] = sum_{m<64} F[u,m] * G[v,m]
//     F[u,n] = Re(2 dC_n dA_n^{32u}),  F[u,32+n] = Im(...)
//     G[v,n] = Re(dA_n^v),             G[v,32+n] = -Im(dA_n^v)
// Precision: 2-term bf16 truncation split; 3 passes Fh*Gh + Fh*Gl + Fl*Gh.
// SMEM in fragment-major order: word(r,c) = (r>>3)*256 + (c>>2)*32 + (r&7)*4 + (c&3)
// -> every m16n8k16 fragment load is bank-conflict-free (bank = gid*4 + tig).

#define HN  1024
#define NM  32
#define LL  4096
#define TPB 128

__device__ __forceinline__ uint32_t pack_hi16(float a, float b) {
    uint32_t r;
    asm("prmt.b32 %0, %1, %2, 0x7632;"
        : "=r"(r) : "r"(__float_as_uint(a)), "r"(__float_as_uint(b)));
    return r;
}

__device__ __forceinline__ void mma16816(float* c, uint32_t a0, uint32_t a1,
                                         uint32_t a2, uint32_t a3,
                                         uint32_t b0, uint32_t b1) {
    asm volatile(
        "mma.sync.aligned.m16n8k16.row.col.f32.bf16.bf16.f32 "
        "{%0,%1,%2,%3}, {%4,%5,%6,%7}, {%8,%9}, {%0,%1,%2,%3};"
        : "+f"(c[0]), "+f"(c[1]), "+f"(c[2]), "+f"(c[3])
        : "r"(a0), "r"(a1), "r"(a2), "r"(a3), "r"(b0), "r"(b1));
}

// fragment-major word offset, 8-row x 4-wordcol micro-tiles
#define WOFF(r, c) ((((r) >> 3) << 8) + ((((c) >> 2)) << 5) + (((r) & 7) << 2) + ((c) & 3))

__global__ void __launch_bounds__(TPB)
s4d_hmma_kernel(const float* __restrict__ log_dt,      // (H)
                const float* __restrict__ C_real,      // (1,H,NM,2)
                const float* __restrict__ log_A_real,  // (H,NM)
                const float* __restrict__ A_imag,      // (H,NM)
                float* __restrict__ out)               // (1,H,L)
{
    // A: 128 rows x 32 words (64 bf16 K-cols); B: 32 rows x 32 words
    __shared__ uint32_t sAh[128 * 32], sAl[128 * 32];   // 16 KB each
    __shared__ uint16_t sBh[32 * 64], sBl[32 * 64];     // 4 KB each (halfword view)
    __shared__ float T2r[16][33], T2i[16][33];          // Z^b, Z = dA^32
    __shared__ float Ur[8][33],  Ui[8][33];             // 2*dC * Z^(16a)

    const int h = blockIdx.x;
    const int t = threadIdx.x;

    if (t < NM) {
        const int m = t;
        const float dt  = expf(log_dt[h]);
        const float Aor = -expf(log_A_real[h * NM + m]);
        const float Aoi = A_imag[h * NM + m];
        const float dtAr = Aor * dt, dtAi = Aoi * dt;
        const float denr = 1.0f - 0.5f * dtAr;
        const float deni = -0.5f * dtAi;
        const float inv  = 1.0f / (denr * denr + deni * deni);
        const float Br = dt * denr * inv;
        const float Bi = -dt * deni * inv;
        const float Cr = C_real[(h * NM + m) * 2 + 0];
        const float Ci = C_real[(h * NM + m) * 2 + 1];
        const float dCr = 2.0f * (Cr * Br - Ci * Bi);   // factor 2 baked in
        const float dCi = 2.0f * (Cr * Bi + Ci * Br);
        const float numr = 1.0f + 0.5f * dtAr;
        const float numi = 0.5f * dtAi;
        const float dAr = (numr * denr + numi * deni) * inv;
        const float dAi = (numi * denr - numr * deni) * inv;

        // ---- B tiles: G[v][m] = Re(dA^v), G[v][32+m] = -Im(dA^v), hi/lo split
        {
            const int cRe = m >> 1, cIm = 16 + (m >> 1), half = m & 1;
            float wr = 1.0f, wi = 0.0f;
            #pragma unroll 1
            for (int v = 0; v < 32; ++v) {
                const int iRe = (WOFF(v, cRe) << 1) + half;
                const int iIm = (WOFF(v, cIm) << 1) + half;
                const uint32_t xr = __float_as_uint(wr);
                const float hr = __uint_as_float(xr & 0xFFFF0000u);
                sBh[iRe] = (uint16_t)(xr >> 16);
                sBl[iRe] = (uint16_t)(__float_as_uint(wr - hr) >> 16);
                const float niv = -wi;
                const uint32_t xi = __float_as_uint(niv);
                const float hi = __uint_as_float(xi & 0xFFFF0000u);
                sBh[iIm] = (uint16_t)(xi >> 16);
                sBl[iIm] = (uint16_t)(__float_as_uint(niv - hi) >> 16);
                const float nr = wr * dAr - wi * dAi;
                wi = wr * dAi + wi * dAr;
                wr = nr;
            }
        }
        // ---- Z = dA^32
        float zr = dAr, zi = dAi;
        #pragma unroll
        for (int j = 0; j < 5; ++j) {
            const float nr = zr * zr - zi * zi;
            zi = 2.0f * zr * zi;
            zr = nr;
        }
        // T2[b] = Z^b; afterwards (wr,wi) = Z^16
        float wr = 1.0f, wi = 0.0f;
        #pragma unroll
        for (int b = 0; b < 16; ++b) {
            T2r[b][m] = wr; T2i[b][m] = wi;
            const float nr = wr * zr - wi * zi;
            wi = wr * zi + wi * zr;
            wr = nr;
        }
        const float z16r = wr, z16i = wi;
        // U[a] = 2*dC * Z^(16a)
        float yr = dCr, yi = dCi;
        #pragma unroll
        for (int a = 0; a < 8; ++a) {
            Ur[a][m] = yr; Ui[a][m] = yi;
            const float nr = yr * z16r - yi * z16i;
            yi = yr * z16i + yi * z16r;
            yr = nr;
        }
    }
    __syncthreads();

    // ---- A tiles: thread t = row u. P = U[u>>4] * T2[u&15].
    {
        const int aI = t >> 4, bI = t & 15;
        #pragma unroll
        for (int j = 0; j < 16; ++j) {
            const int n0 = 2 * j, n1 = 2 * j + 1;
            const float u0r = Ur[aI][n0], u0i = Ui[aI][n0];
            const float t0r = T2r[bI][n0], t0i = T2i[bI][n0];
            const float p0r = u0r * t0r - u0i * t0i;
            const float p0i = u0r * t0i + u0i * t0r;
            const float u1r = Ur[aI][n1], u1i = Ui[aI][n1];
            const float t1r = T2r[bI][n1], t1i = T2i[bI][n1];
            const float p1r = u1r * t1r - u1i * t1i;
            const float p1i = u1r * t1i + u1i * t1r;
            const float h0r = __uint_as_float(__float_as_uint(p0r) & 0xFFFF0000u);
            const float h1r = __uint_as_float(__float_as_uint(p1r) & 0xFFFF0000u);
            const float h0i = __uint_as_float(__float_as_uint(p0i) & 0xFFFF0000u);
            const float h1i = __uint_as_float(__float_as_uint(p1i) & 0xFFFF0000u);
            const int wRe = WOFF(t, j);        // K cols 2j, 2j+1 (Re modes n0, n1)
            const int wIm = WOFF(t, 16 + j);   // K cols 32+2j   (Im modes)
            sAh[wRe] = pack_hi16(p0r, p1r);
            sAh[wIm] = pack_hi16(p0i, p1i);
            sAl[wRe] = pack_hi16(p0r - h0r, p1r - h1r);
            sAl[wIm] = pack_hi16(p0i - h0i, p1i - h1i);
        }
    }
    __syncthreads();

    // ---- MMA mainloop: warp w -> rows [32w, 32w+32)
    const int lane = t & 31;
    const int wid  = t >> 5;
    const int gid  = lane >> 2;
    const int tig  = lane & 3;
    const int lbase = gid * 4 + tig;       // fragment-major lane offset
    const int arow  = wid * 4;             // (r0 >> 3)

    float acc[2][4][4] = {};

    const uint32_t* Aat[3] = { sAh, sAh, sAl };
    const uint32_t* Bat[3] = { (const uint32_t*)sBh, (const uint32_t*)sBl,
                               (const uint32_t*)sBh };

    #pragma unroll
    for (int s = 0; s < 3; ++s) {
        const uint32_t* A = Aat[s];
        const uint32_t* B = Bat[s];
        #pragma unroll
        for (int ks = 0; ks < 4; ++ks) {
            uint32_t b0[4], b1[4];
            #pragma unroll
            for (int nt = 0; nt < 4; ++nt) {
                const int w = nt * 256 + ks * 64 + lbase;
                b0[nt] = B[w];
                b1[nt] = B[w + 32];
            }
            #pragma unroll
            for (int mt = 0; mt < 2; ++mt) {
                const int w = (arow + mt * 2) * 256 + ks * 64 + lbase;
                const uint32_t a0 = A[w];
                const uint32_t a1 = A[w + 256];
                const uint32_t a2 = A[w + 32];
                const uint32_t a3 = A[w + 256 + 32];
                #pragma unroll
                for (int nt = 0; nt < 4; ++nt)
                    mma16816(acc[mt][nt], a0, a1, a2, a3, b0[nt], b1[nt]);
            }
        }
    }

    // ---- Epilogue: C[gid][tig*2 +0/1] and C[gid+8][...] per (mt, nt) tile
    float* __restrict__ o = out + (size_t)h * LL;
    const int r0 = wid * 32;
    #pragma unroll
    for (int mt = 0; mt < 2; ++mt) {
        const int u0 = r0 + mt * 16 + gid;
        #pragma unroll
        for (int nt = 0; nt < 4; ++nt) {
            const int v = nt * 8 + tig * 2;
            *reinterpret_cast<float2*>(o + (size_t)u0 * 32 + v) =
                make_float2(acc[mt][nt][0], acc[mt][nt][1]);
            *reinterpret_cast<float2*>(o + (size_t)(u0 + 8) * 32 + v) =
                make_float2(acc[mt][nt][2], acc[mt][nt][3]);
        }
    }
}

extern "C" void kernel_launch(void* const* d_in, const int* in_sizes, int n_in,
                              void* d_out, int out_size) {
    const float* log_dt     = (const float*)d_in[0];
    const float* C_real     = (const float*)d_in[1];
    const float* log_A_real = (const float*)d_in[2];
    const float* A_imag     = (const float*)d_in[3];
    float* out = (float*)d_out;
    s4d_hmma_kernel<<<HN, TPB>>>(log_dt, C_real, log_A_real, A_imag, out);
}